// round 5
// baseline (speedup 1.0000x reference)
#include <cuda_runtime.h>
#include <cuda_bf16.h>
#include <cstdint>

// Shape: masks [16,512,1024,4] f32, src_stft [16,512,2048,4] f32.
// loss = mean |masks - onehot(argmax_C src_stft[:,:,:1024,:])|
//
// Identity used (masks strictly in [0,1)):
//   sum_c |m_c - onehot_c| = (sum_c m_c) + 1 - 2*m_{argmax}
// so we accumulate (sum_m - 2*m_sel) per group and add NG once at the end.

static constexpr int   NG      = 16 * 512 * 1024;      // 8,388,608 groups
static constexpr int   THREADS = 256;
static constexpr int   BLOCKS  = 148 * 8;              // exactly one resident wave
static constexpr int   STRIDE  = THREADS * BLOCKS;     // 303,104
static constexpr float INV_N   = 1.0f / 33554432.0f;   // 1 / 2^25 (exact)

__device__ float        g_partial;  // zero-init at module load; reset each run
__device__ unsigned int g_count;

__global__ __launch_bounds__(THREADS) void recon_loss_kernel(
    const float4* __restrict__ masks,
    const float4* __restrict__ stft,
    float* __restrict__ out)
{
    float acc = 0.0f;
    int i = blockIdx.x * THREADS + threadIdx.x;

    #pragma unroll 4
    for (; i < NG; i += STRIDE) {
        // i = bt*1024 + f ; gt group lives at bt*2048 + f (first half of dim 2)
        const int bt = i >> 10;
        const int f  = i & 1023;
        const float4 g = __ldcs(&stft[(bt << 11) + f]);   // single-use stream
        const float4 m = __ldcs(&masks[i]);

        // first-max argmax over C=4 (strict > keeps earliest index),
        // carrying the corresponding mask component.
        float best = g.x, msel = m.x;
        if (g.y > best) { best = g.y; msel = m.y; }
        if (g.z > best) { best = g.z; msel = m.z; }
        if (g.w > best) { best = g.w; msel = m.w; }

        acc += (m.x + m.y) + (m.z + m.w) - 2.0f * msel;
    }

    // warp reduce
    #pragma unroll
    for (int off = 16; off > 0; off >>= 1)
        acc += __shfl_xor_sync(0xFFFFFFFFu, acc, off);

    __shared__ float warp_sums[THREADS / 32];
    const int lane = threadIdx.x & 31;
    const int wid  = threadIdx.x >> 5;
    if (lane == 0) warp_sums[wid] = acc;
    __syncthreads();

    if (wid == 0) {
        float s = (lane < THREADS / 32) ? warp_sums[lane] : 0.0f;
        #pragma unroll
        for (int off = 4; off > 0; off >>= 1)
            s += __shfl_xor_sync(0xFFFFFFFFu, s, off);

        if (lane == 0) {
            atomicAdd(&g_partial, s);
            __threadfence();
            const unsigned done = atomicAdd(&g_count, 1u);
            if (done == (unsigned)gridDim.x - 1u) {
                // Last block: read-and-reset so graph replays stay deterministic.
                const float total = atomicExch(&g_partial, 0.0f);
                atomicExch(&g_count, 0u);
                // + NG accounts for the "+1 per group" term of the identity.
                out[0] = (total + (float)NG) * INV_N;
            }
        }
    }
}

extern "C" void kernel_launch(void* const* d_in, const int* in_sizes, int n_in,
                              void* d_out, int out_size)
{
    const float4* masks = (const float4*)d_in[0];
    const float4* stft  = (const float4*)d_in[1];
    float* out = (float*)d_out;

    recon_loss_kernel<<<BLOCKS, THREADS>>>(masks, stft, out);
}

// round 6
// speedup vs baseline: 1.0064x; 1.0064x over previous
#include <cuda_runtime.h>
#include <cuda_bf16.h>
#include <cstdint>

// Shape: masks [16,512,1024,4] f32, src_stft [16,512,2048,4] f32.
// loss = mean |masks - onehot(argmax_C src_stft[:,:,:1024,:])|
//
// Identity (masks in [0,1)):  sum_c |m_c - onehot_c| = (sum_c m_c) + 1 - 2*m_{argmax}
// -> accumulate (sum_m - 2*m_sel) per group, add NG once at the end.

static constexpr int   NG      = 16 * 512 * 1024;      // 8,388,608 float4 groups
static constexpr int   THREADS = 256;
static constexpr int   BLOCKS  = 148 * 16;             // 2368 (R1's best-BW grid)
static constexpr int   STRIDE  = THREADS * BLOCKS;
static constexpr float INV_N   = 1.0f / 33554432.0f;   // 1 / 2^25 (exact)

__device__ float        g_partial;  // zero at module load; reset by last block
__device__ unsigned int g_count;

__global__ __launch_bounds__(THREADS) void recon_loss_kernel(
    const float4* __restrict__ masks,
    const float4* __restrict__ stft,
    float* __restrict__ out)
{
    float acc = 0.0f;
    int i = blockIdx.x * THREADS + threadIdx.x;

    #pragma unroll 4
    for (; i < NG; i += STRIDE) {
        // i = bt*1024 + f ; gt group lives at bt*2048 + f (first half of dim 2)
        const int bt = i >> 10;
        const int f  = i & 1023;
        const float4 g = __ldg(&stft[(bt << 11) + f]);  // default policy: best BW
        const float4 m = __ldg(&masks[i]);

        // first-max argmax over C=4 (strict > keeps earliest index),
        // carrying the matching mask component.
        float best = g.x, msel = m.x;
        if (g.y > best) { best = g.y; msel = m.y; }
        if (g.z > best) { best = g.z; msel = m.z; }
        if (g.w > best) { best = g.w; msel = m.w; }

        acc += (m.x + m.y) + (m.z + m.w) - 2.0f * msel;
    }

    // warp reduce
    #pragma unroll
    for (int off = 16; off > 0; off >>= 1)
        acc += __shfl_xor_sync(0xFFFFFFFFu, acc, off);

    __shared__ float warp_sums[THREADS / 32];
    const int lane = threadIdx.x & 31;
    const int wid  = threadIdx.x >> 5;
    if (lane == 0) warp_sums[wid] = acc;
    __syncthreads();

    if (wid == 0) {
        float s = (lane < THREADS / 32) ? warp_sums[lane] : 0.0f;
        #pragma unroll
        for (int off = 4; off > 0; off >>= 1)
            s += __shfl_xor_sync(0xFFFFFFFFu, s, off);

        if (lane == 0) {
            atomicAdd(&g_partial, s);
            __threadfence();
            const unsigned done = atomicAdd(&g_count, 1u);
            if (done == (unsigned)gridDim.x - 1u) {
                // Last block: read-and-reset so graph replays stay deterministic.
                const float total = atomicExch(&g_partial, 0.0f);
                atomicExch(&g_count, 0u);
                out[0] = (total + (float)NG) * INV_N;  // +NG = "+1 per group"
            }
        }
    }
}

extern "C" void kernel_launch(void* const* d_in, const int* in_sizes, int n_in,
                              void* d_out, int out_size)
{
    const float4* masks = (const float4*)d_in[0];
    const float4* stft  = (const float4*)d_in[1];
    float* out = (float*)d_out;

    recon_loss_kernel<<<BLOCKS, THREADS>>>(masks, stft, out);
}